// round 1
// baseline (speedup 1.0000x reference)
#include <cuda_runtime.h>

// ---------------------------------------------------------------------------
// Amortized VI ELBO kernel.
// Inputs (metadata order): y[N,2], zs[N,8,4],
//   mu_{W1,b1,W2,b2,W3,b3}, ld_{...}, lo_{...}
// Output: single float = mean over N of (datafit + entropy).
// ---------------------------------------------------------------------------

#define NTHREADS 256
#define MAX_BLOCKS 8192

__device__ double g_partial[MAX_BLOCKS];

// Per-sample constant: Cprior + Clik
//   Cprior = -(log .25 + 3 log .5) - 2*log(2pi) = -0.21001823
//   Clik   = 2*(-log .01 - .5*log(2pi))        =  7.37246331
#define C_PER_SAMPLE 7.1624450756f
// Entropy constant: 0.5*4*(1+log 2pi)
#define C_ENTROPY 5.6757541328f

struct MlpSmem {
    float w1a[20];   // W1 row 0
    float w1b[20];   // W1 row 1
    float b1[20];
    float w2t[200];  // transposed [10][20], 16B-aligned rows
    float b2[12];    // padded
    float w3t[72];   // transposed padded [out<=6][12]
    float b3[8];     // padded
};

__device__ __forceinline__ float relu_f(float x) { return fmaxf(x, 0.0f); }

__device__ __forceinline__ void load_mlp(
    MlpSmem* s, const float* W1, const float* B1,
    const float* W2, const float* B2,
    const float* W3, const float* B3, int OUT, int tid)
{
    if (tid < 20) {
        s->w1a[tid] = W1[tid];
        s->w1b[tid] = W1[20 + tid];
        s->b1[tid]  = B1[tid];
    }
    for (int i = tid; i < 200; i += NTHREADS) {
        int k = i / 20, j = i % 20;          // w2t[k][j] = W2[j][k]
        s->w2t[i] = W2[j * 10 + k];
    }
    if (tid < 12) s->b2[tid] = (tid < 10) ? B2[tid] : 0.0f;
    for (int i = tid; i < OUT * 12; i += NTHREADS) {
        int o = i / 12, k = i % 12;          // w3t[o][k] = W3[k][o]
        s->w3t[i] = (k < 10) ? W3[k * OUT + o] : 0.0f;
    }
    if (tid < 8) s->b3[tid] = (tid < OUT) ? B3[tid] : 0.0f;
}

template <int OUT>
__device__ __forceinline__ void mlp_eval(const MlpSmem* w, float y0, float y1,
                                         float* out)
{
    float h1[20];
#pragma unroll
    for (int j = 0; j < 20; j++)
        h1[j] = relu_f(fmaf(w->w1a[j], y0, fmaf(w->w1b[j], y1, w->b1[j])));

    float h2[12];
#pragma unroll
    for (int k = 0; k < 10; k++) {
        const float4* wr = (const float4*)(&w->w2t[k * 20]);
        float acc = w->b2[k];
#pragma unroll
        for (int q = 0; q < 5; q++) {
            float4 v = wr[q];
            acc = fmaf(v.x, h1[4 * q + 0], acc);
            acc = fmaf(v.y, h1[4 * q + 1], acc);
            acc = fmaf(v.z, h1[4 * q + 2], acc);
            acc = fmaf(v.w, h1[4 * q + 3], acc);
        }
        h2[k] = relu_f(acc);
    }
    h2[10] = 0.0f; h2[11] = 0.0f;

#pragma unroll
    for (int o = 0; o < OUT; o++) {
        const float4* wr = (const float4*)(&w->w3t[o * 12]);
        float acc = w->b3[o];
#pragma unroll
        for (int q = 0; q < 3; q++) {
            float4 v = wr[q];
            acc = fmaf(v.x, h2[4 * q + 0], acc);
            acc = fmaf(v.y, h2[4 * q + 1], acc);
            acc = fmaf(v.z, h2[4 * q + 2], acc);
            acc = fmaf(v.w, h2[4 * q + 3], acc);
        }
        out[o] = acc;
    }
}

__device__ __forceinline__ float softplus_f(float x)
{
    return fmaxf(x, 0.0f) + log1pf(__expf(-fabsf(x)));
}

__global__ void __launch_bounds__(NTHREADS)
vi_kernel(const float* __restrict__ y, const float* __restrict__ zs, int N,
          const float* mW1, const float* mb1, const float* mW2,
          const float* mb2, const float* mW3, const float* mb3,
          const float* dW1, const float* db1, const float* dW2,
          const float* db2, const float* dW3, const float* db3,
          const float* oW1, const float* ob1, const float* oW2,
          const float* ob2, const float* oW3, const float* ob3)
{
    __shared__ MlpSmem smu, sld, slo;
    int tid = threadIdx.x;
    load_mlp(&smu, mW1, mb1, mW2, mb2, mW3, mb3, 4, tid);
    load_mlp(&sld, dW1, db1, dW2, db2, dW3, db3, 4, tid);
    load_mlp(&slo, oW1, ob1, oW2, ob2, oW3, ob3, 6, tid);
    __syncthreads();

    int n = blockIdx.x * NTHREADS + tid;
    float val = 0.0f;
    if (n < N) {
        float2 yv = ((const float2*)y)[n];
        float mu[4], ldr[4], off[6];
        mlp_eval<4>(&smu, yv.x, yv.y, mu);
        mlp_eval<4>(&sld, yv.x, yv.y, ldr);
        mlp_eval<6>(&slo, yv.x, yv.y, off);

        float d0 = softplus_f(ldr[0]);
        float d1 = softplus_f(ldr[1]);
        float d2 = softplus_f(ldr[2]);
        float d3 = softplus_f(ldr[3]);

        const float4* zp = (const float4*)zs + (size_t)n * 8;

        float acc = 0.0f;
#pragma unroll
        for (int p = 0; p < 8; p++) {
            float4 z = zp[p];
            float xi0 = fmaf(d0, z.x, mu[0]);
            float xi1 = fmaf(d1, z.y, fmaf(off[0], z.x, mu[1]));
            float xi2 = fmaf(d2, z.z, fmaf(off[2], z.y, fmaf(off[1], z.x, mu[2])));
            float xi3 = fmaf(d3, z.w, fmaf(off[5], z.z,
                          fmaf(off[4], z.y, fmaf(off[3], z.x, mu[3]))));

            float a1 = xi1;
            float a2 = a1 + xi2;
            float a3 = a2 + xi3;
            float s1, c1, s2, c2, s3, c3;
            __sincosf(a1, &s1, &c1);
            __sincosf(a2, &s2, &c2);
            __sincosf(a3, &s3, &c3);

            float px = fmaf(0.5f, c1, fmaf(0.5f, c2, c3));
            float py = xi0 + fmaf(0.5f, s1, fmaf(0.5f, s2, s3));

            // prior: -0.5 * sum (xi_i / prior_scale_i)^2  (consts folded)
            float t0 = xi0 * 4.0f;
            float t1 = xi1 * 2.0f;
            float t2 = xi2 * 2.0f;
            float t3 = xi3 * 2.0f;
            float q = fmaf(t0, t0, fmaf(t1, t1, fmaf(t2, t2, t3 * t3)));

            // likelihood residuals, /0.01 == *100
            float rx = (yv.x - px) * 100.0f;
            float ry = (yv.y - py) * 100.0f;
            float r2 = fmaf(rx, rx, ry * ry);

            acc = fmaf(-0.5f, q + r2, acc);
        }

        float datafit = fmaf(acc, 0.125f, C_PER_SAMPLE);
        float entropy = C_ENTROPY + __logf(d0) + __logf(d1) +
                        __logf(d2) + __logf(d3);
        val = datafit + entropy;
    }

    // block reduction -> deterministic per-block double partial
#pragma unroll
    for (int o = 16; o > 0; o >>= 1)
        val += __shfl_down_sync(0xffffffffu, val, o);
    __shared__ float wsum[NTHREADS / 32];
    if ((tid & 31) == 0) wsum[tid >> 5] = val;
    __syncthreads();
    if (tid == 0) {
        double s = 0.0;
#pragma unroll
        for (int w = 0; w < NTHREADS / 32; w++) s += (double)wsum[w];
        g_partial[blockIdx.x] = s;
    }
}

__global__ void finalize_kernel(float* out, int nblocks, int N)
{
    __shared__ double sh[256];
    double s = 0.0;
    for (int i = threadIdx.x; i < nblocks; i += 256) s += g_partial[i];
    sh[threadIdx.x] = s;
    __syncthreads();
    for (int stride = 128; stride > 0; stride >>= 1) {
        if (threadIdx.x < stride) sh[threadIdx.x] += sh[threadIdx.x + stride];
        __syncthreads();
    }
    if (threadIdx.x == 0) out[0] = (float)(sh[0] / (double)N);
}

extern "C" void kernel_launch(void* const* d_in, const int* in_sizes, int n_in,
                              void* d_out, int out_size)
{
    const float* y  = (const float*)d_in[0];
    const float* zs = (const float*)d_in[1];
    int N = in_sizes[0] / 2;
    int nblocks = (N + NTHREADS - 1) / NTHREADS;
    if (nblocks > MAX_BLOCKS) nblocks = MAX_BLOCKS;  // N<=2M supported

    vi_kernel<<<nblocks, NTHREADS>>>(
        y, zs, N,
        (const float*)d_in[2],  (const float*)d_in[3],  (const float*)d_in[4],
        (const float*)d_in[5],  (const float*)d_in[6],  (const float*)d_in[7],
        (const float*)d_in[8],  (const float*)d_in[9],  (const float*)d_in[10],
        (const float*)d_in[11], (const float*)d_in[12], (const float*)d_in[13],
        (const float*)d_in[14], (const float*)d_in[15], (const float*)d_in[16],
        (const float*)d_in[17], (const float*)d_in[18], (const float*)d_in[19]);

    finalize_kernel<<<1, 256>>>((float*)d_out, nblocks, N);
}